// round 1
// baseline (speedup 1.0000x reference)
#include <cuda_runtime.h>
#include <math.h>

#define BATCH 4
#define NPT   1024
#define HID   64
#define HEADS 16
#define NB    1280          // LUT bins
#define TPB   512

// ---------------- device scratch (no allocations allowed) ----------------
__device__ float  g_invh;                       // NB / range
__device__ float  g_h;                          // range / NB
__device__ float  g_nodes[(NB + 1) * HEADS];    // f_k at nodes
__device__ float4 g_tab[NB * 8];                // per bin: 8 x {a_2m, s_2m, a_2m+1, s_2m+1}

// ---------------- K1: distance range = 2 * max ||c|| ----------------
__global__ void k_range(const float* __restrict__ coords) {
    __shared__ float red[256];
    float mx = 0.0f;
    for (int idx = threadIdx.x; idx < BATCH * NPT; idx += 256) {
        float x = coords[idx * 3 + 0];
        float y = coords[idx * 3 + 1];
        float z = coords[idx * 3 + 2];
        mx = fmaxf(mx, fmaf(x, x, fmaf(y, y, z * z)));
    }
    red[threadIdx.x] = mx;
    __syncthreads();
    for (int s = 128; s > 0; s >>= 1) {
        if (threadIdx.x < s) red[threadIdx.x] = fmaxf(red[threadIdx.x], red[threadIdx.x + s]);
        __syncthreads();
    }
    if (threadIdx.x == 0) {
        float range = fmaxf(2.0f * sqrtf(red[0]) * 1.0002f, 1e-6f);
        g_invh = (float)NB / range;
        g_h    = range / (float)NB;
    }
}

// ---------------- K2: evaluate f_k(d) at NB+1 nodes in fp64 ----------------
__global__ void k_nodes(const float* __restrict__ w1, const float* __restrict__ b1,
                        const float* __restrict__ w2, const float* __restrict__ b2) {
    int node = blockIdx.x * blockDim.x + threadIdx.x;
    if (node > NB) return;
    double d = (double)g_h * (double)node;
    double acc[HEADS];
    #pragma unroll
    for (int k = 0; k < HEADS; k++) acc[k] = (double)b2[k];
    for (int h = 0; h < HID; h++) {
        double z = d * (double)w1[h] + (double)b1[h];
        double s = z / (1.0 + exp(-z));               // silu
        #pragma unroll
        for (int k = 0; k < HEADS; k++) acc[k] += s * (double)w2[h * HEADS + k];
    }
    #pragma unroll
    for (int k = 0; k < HEADS; k++) g_nodes[node * HEADS + k] = (float)acc[k];
}

// ---------------- K3: pack {value, slope} interleaved per bin ----------------
__global__ void k_tab() {
    int idx = blockIdx.x * blockDim.x + threadIdx.x;   // bin*8 + m
    if (idx >= NB * 8) return;
    int bin = idx >> 3, m = idx & 7;
    int k0 = 2 * m;
    float a0 = g_nodes[bin * HEADS + k0];
    float a1 = g_nodes[bin * HEADS + k0 + 1];
    float n0 = g_nodes[(bin + 1) * HEADS + k0];
    float n1 = g_nodes[(bin + 1) * HEADS + k0 + 1];
    g_tab[idx] = make_float4(a0, n0 - a0, a1, n1 - a1);
}

// ---------------- K4: main pair kernel ----------------
// Persistent blocks; shared = swizzled LUT (160KB) + all coords (48KB).
// Block handles 2 rows (b,i) per iteration: tid<256 -> row0, else row1.
// Each thread handles 4 consecutive j, writes 16 x STG.128 (coalesced in j).
__global__ __launch_bounds__(TPB, 1)
void k_main(const float* __restrict__ coords, float* __restrict__ out) {
    extern __shared__ float smem[];
    float4* stab   = (float4*)smem;                 // NB*8 float4
    float*  scoord = smem + NB * 32;                // BATCH*NPT*3 floats

    // Load table with per-bin XOR swizzle of the 16B quarters (bank spreading).
    for (int idx = threadIdx.x; idx < NB * 8; idx += TPB) {
        int bin = idx >> 3, lq = idx & 7;
        stab[(bin << 3) | (lq ^ (bin & 7))] = g_tab[idx];
    }
    for (int idx = threadIdx.x; idx < BATCH * NPT * 3; idx += TPB)
        scoord[idx] = coords[idx];
    __syncthreads();

    const float invh = g_invh;
    const int half = threadIdx.x >> 8;          // 0/1 -> which row of the pair
    const int q    = threadIdx.x & 255;
    const int j0   = q << 2;
    const int NN   = NPT * NPT;

    for (int rp = blockIdx.x; rp < (BATCH * NPT) / 2; rp += gridDim.x) {
        int row = 2 * rp + half;
        int b = row >> 10;
        int i = row & 1023;
        const float* cb = scoord + b * NPT * 3;
        float cix = cb[i * 3 + 0];
        float ciy = cb[i * 3 + 1];
        float ciz = cb[i * 3 + 2];

        float4 v[HEADS];
        #pragma unroll
        for (int p = 0; p < 4; p++) {
            int j = j0 + p;
            float dx = cix - cb[j * 3 + 0];
            float dy = ciy - cb[j * 3 + 1];
            float dz = ciz - cb[j * 3 + 2];
            float d  = sqrtf(fmaf(dx, dx, fmaf(dy, dy, dz * dz)));
            float x  = d * invh;
            int bin  = (int)x;
            bin = min(bin, NB - 1);
            float t  = x - (float)bin;
            const float4* e = stab + (bin << 3);
            int sw = bin & 7;
            #pragma unroll
            for (int lq = 0; lq < 8; lq++) {
                float4 w = e[lq ^ sw];
                float o0 = fmaf(t, w.y, w.x);
                float o1 = fmaf(t, w.w, w.z);
                int k = 2 * lq;
                if      (p == 0) { v[k].x = o0; v[k + 1].x = o1; }
                else if (p == 1) { v[k].y = o0; v[k + 1].y = o1; }
                else if (p == 2) { v[k].z = o0; v[k + 1].z = o1; }
                else             { v[k].w = o0; v[k + 1].w = o1; }
            }
        }

        float4* po = (float4*)(out + (size_t)b * HEADS * NN + (size_t)i * NPT + j0);
        #pragma unroll
        for (int k = 0; k < HEADS; k++) {
            *po = v[k];
            po += NN / 4;
        }
    }
}

// ---------------- launch ----------------
extern "C" void kernel_launch(void* const* d_in, const int* in_sizes, int n_in,
                              void* d_out, int out_size) {
    const float* coords = (const float*)d_in[0];
    const float* w1     = (const float*)d_in[1];
    const float* b1     = (const float*)d_in[2];
    const float* w2     = (const float*)d_in[3];
    const float* b2     = (const float*)d_in[4];
    float* out = (float*)d_out;

    const int smem_bytes = NB * 32 * 4 + BATCH * NPT * 3 * 4;   // 163840 + 49152 = 212992
    cudaFuncSetAttribute(k_main, cudaFuncAttributeMaxDynamicSharedMemorySize, smem_bytes);

    k_range<<<1, 256>>>(coords);
    k_nodes<<<(NB + 1 + 127) / 128, 128>>>(w1, b1, w2, b2);
    k_tab<<<(NB * 8 + 255) / 256, 256>>>();
    k_main<<<148, TPB, smem_bytes>>>(coords, out);
}

// round 3
// speedup vs baseline: 1.1812x; 1.1812x over previous
#include <cuda_runtime.h>
#include <math.h>

#define BATCH 4
#define NPT   1024
#define HID   64
#define HEADS 16
#define NB    1280
#define TPB   1024

// ---------------- device scratch ----------------
__device__ float  g_invh;
__device__ float  g_h;
__device__ float  g_nodes[(NB + 1) * HEADS];     // f_k at nodes
__device__ float4 g_cpad[BATCH * NPT];           // padded coords

// ---------------- K1: range + pad coords ----------------
__global__ void k_prep(const float* __restrict__ coords) {
    __shared__ float red[256];
    float mx = 0.0f;
    for (int idx = threadIdx.x; idx < BATCH * NPT; idx += 256) {
        float x = coords[idx * 3 + 0];
        float y = coords[idx * 3 + 1];
        float z = coords[idx * 3 + 2];
        g_cpad[idx] = make_float4(x, y, z, 0.0f);
        mx = fmaxf(mx, fmaf(x, x, fmaf(y, y, z * z)));
    }
    red[threadIdx.x] = mx;
    __syncthreads();
    for (int s = 128; s > 0; s >>= 1) {
        if (threadIdx.x < s) red[threadIdx.x] = fmaxf(red[threadIdx.x], red[threadIdx.x + s]);
        __syncthreads();
    }
    if (threadIdx.x == 0) {
        float range = fmaxf(2.0f * sqrtf(red[0]) * 1.0002f, 1e-6f);
        g_invh = (float)NB / range;
        g_h    = range / (float)NB;
    }
}

// ---------------- K2: node values, fp32 ----------------
__global__ void k_nodes(const float* __restrict__ w1, const float* __restrict__ b1,
                        const float* __restrict__ w2, const float* __restrict__ b2) {
    int node = blockIdx.x * blockDim.x + threadIdx.x;
    if (node > NB) return;
    float d = g_h * (float)node;
    float acc[HEADS];
    #pragma unroll
    for (int k = 0; k < HEADS; k++) acc[k] = b2[k];
    #pragma unroll 4
    for (int h = 0; h < HID; h++) {
        float z = fmaf(d, w1[h], b1[h]);
        float s = z / (1.0f + expf(-z));          // silu
        #pragma unroll
        for (int k = 0; k < HEADS; k++) acc[k] = fmaf(s, w2[h * HEADS + k], acc[k]);
    }
    #pragma unroll
    for (int k = 0; k < HEADS; k++) g_nodes[node * HEADS + k] = acc[k];
}

// ---------------- K3: main kernel ----------------
// Shared = swizzled LUT only (160 KB). Coords from registers / broadcast LDG.
// 1024 threads: 4 rows per iteration (half = tid>>8), thread owns 4 consecutive j.
// lq-outer loop: load 4 LUT entries, lerp, store 2 x STG.128 immediately.
__global__ __launch_bounds__(TPB, 1)
void k_main(float* __restrict__ out) {
    extern __shared__ float4 stab[];   // NB*8 entries, xor-swizzled quarters

    // Fill LUT with slopes computed inline from g_nodes.
    for (int idx = threadIdx.x; idx < NB * 8; idx += TPB) {
        int bin = idx >> 3, m = idx & 7, k0 = 2 * m;
        const float* np = g_nodes + bin * HEADS + k0;
        float a0 = np[0],      a1 = np[1];
        float n0 = np[HEADS],  n1 = np[HEADS + 1];
        stab[(bin << 3) | (m ^ (bin & 7))] = make_float4(a0, n0 - a0, a1, n1 - a1);
    }
    __syncthreads();

    const float invh = g_invh;
    const int half = threadIdx.x >> 8;        // 0..3 : row within group
    const int q    = threadIdx.x & 255;       // j-group
    const int NNq  = NPT * NPT / 4;

    // Balanced contiguous chunk of row-groups per block.
    const int ngrp = (BATCH * NPT) / 4;       // 1024 groups of 4 rows
    int base = ngrp / gridDim.x;              // 6
    int rem  = ngrp % gridDim.x;              // 136
    int start, cnt;
    if (blockIdx.x < rem) { cnt = base + 1; start = blockIdx.x * cnt; }
    else                  { cnt = base;     start = rem * (base + 1) + (blockIdx.x - rem) * base; }
    int end = start + cnt;

    int bcur = -1;
    float4 cj0, cj1, cj2, cj3;

    for (int rp = start; rp < end; rp++) {
        int b = rp >> 8;
        if (b != bcur) {
            bcur = b;
            const float4* cp = g_cpad + b * NPT + (q << 2);
            cj0 = cp[0]; cj1 = cp[1]; cj2 = cp[2]; cj3 = cp[3];
        }
        int i = (((rp & 255) << 2) | half);
        float4 ci = __ldg(&g_cpad[b * NPT + i]);   // broadcast within warp

        float t[4];
        int   a[4];
        #define PAIR(p, cj) { \
            float dx = ci.x - cj.x, dy = ci.y - cj.y, dz = ci.z - cj.z; \
            float x  = sqrtf(fmaf(dx, dx, fmaf(dy, dy, dz * dz))) * invh; \
            int bin  = min((int)x, NB - 1); \
            t[p] = x - (float)bin; \
            a[p] = (bin << 3) | (bin & 7); }
        PAIR(0, cj0) PAIR(1, cj1) PAIR(2, cj2) PAIR(3, cj3)
        #undef PAIR

        float4* po = (float4*)out + (size_t)b * HEADS * NNq + (size_t)i * (NPT / 4) + q;
        #pragma unroll
        for (int lq = 0; lq < 8; lq++) {
            float4 w0 = stab[a[0] ^ lq];
            float4 w1 = stab[a[1] ^ lq];
            float4 w2 = stab[a[2] ^ lq];
            float4 w3 = stab[a[3] ^ lq];
            float4 A = make_float4(fmaf(t[0], w0.y, w0.x), fmaf(t[1], w1.y, w1.x),
                                   fmaf(t[2], w2.y, w2.x), fmaf(t[3], w3.y, w3.x));
            float4 Bv = make_float4(fmaf(t[0], w0.w, w0.z), fmaf(t[1], w1.w, w1.z),
                                    fmaf(t[2], w2.w, w2.z), fmaf(t[3], w3.w, w3.z));
            po[(size_t)(2 * lq)     * NNq] = A;
            po[(size_t)(2 * lq + 1) * NNq] = Bv;
        }
    }
}

// ---------------- launch ----------------
extern "C" void kernel_launch(void* const* d_in, const int* in_sizes, int n_in,
                              void* d_out, int out_size) {
    const float* coords = (const float*)d_in[0];
    const float* w1     = (const float*)d_in[1];
    const float* b1     = (const float*)d_in[2];
    const float* w2     = (const float*)d_in[3];
    const float* b2     = (const float*)d_in[4];
    float* out = (float*)d_out;

    const int smem_bytes = NB * 8 * (int)sizeof(float4);   // 163840
    cudaFuncSetAttribute(k_main, cudaFuncAttributeMaxDynamicSharedMemorySize, smem_bytes);

    k_prep<<<1, 256>>>(coords);
    k_nodes<<<(NB + 1 + 127) / 128, 128>>>(w1, b1, w2, b2);
    k_main<<<148, TPB, smem_bytes>>>(out);
}

// round 5
// speedup vs baseline: 1.3244x; 1.1213x over previous
#include <cuda_runtime.h>
#include <cuda_fp16.h>
#include <math.h>

#define BATCH 4
#define NPT   1024
#define HID   64
#define HEADS 16
#define NB    512
#define TPB   512
#define GRID  296
#define ROWQ  7            // float4 quarters per LUT row (112 B pitch; 96 B used)

// Single fused kernel. Every block:
//   phase 1: max ||c||^2 over all points (associative max -> identical result per block)
//   phase 2: build LUT in smem: per bin, 16 fp32 node values + 16 fp16 slopes
//   phase 3: process contiguous rows; thread owns 2 consecutive j; float2 stores per head.
__global__ __launch_bounds__(TPB, 2)
void k_fused(const float* __restrict__ coords,
             const float* __restrict__ w1, const float* __restrict__ b1,
             const float* __restrict__ w2, const float* __restrict__ b2,
             float* __restrict__ out) {
    extern __shared__ float smem[];                  // (NB+1)*ROWQ*4 floats + 32 red
    float4* lut4 = (float4*)smem;
    float*  red  = smem + (NB + 1) * ROWQ * 4;

    const int tid = threadIdx.x;

    // ---------- phase 1: range ----------
    float mx = 0.0f;
    for (int idx = tid; idx < BATCH * NPT; idx += TPB) {
        float x = coords[idx * 3 + 0];
        float y = coords[idx * 3 + 1];
        float z = coords[idx * 3 + 2];
        mx = fmaxf(mx, fmaf(x, x, fmaf(y, y, z * z)));
    }
    #pragma unroll
    for (int s = 16; s; s >>= 1) mx = fmaxf(mx, __shfl_xor_sync(0xFFFFFFFFu, mx, s));
    if ((tid & 31) == 0) red[tid >> 5] = mx;
    __syncthreads();
    if (tid == 0) {
        float m = red[0];
        #pragma unroll
        for (int w = 1; w < TPB / 32; w++) m = fmaxf(m, red[w]);
        float range = fmaxf(2.0f * sqrtf(m) * 1.0002f, 1e-6f);
        red[16] = (float)NB / range;       // invh
        red[17] = range / (float)NB;       // h
    }
    __syncthreads();
    const float invh  = red[16];
    const float hstep = red[17];

    // ---------- phase 2a: node values (fp32) ----------
    for (int n = tid; n <= NB; n += TPB) {
        float d = hstep * (float)n;
        float acc[HEADS];
        #pragma unroll
        for (int k = 0; k < HEADS; k++) acc[k] = __ldg(&b2[k]);
        #pragma unroll 4
        for (int hh = 0; hh < HID; hh++) {
            float z = fmaf(d, __ldg(&w1[hh]), __ldg(&b1[hh]));
            float s = z / (1.0f + expf(-z));                // silu
            #pragma unroll
            for (int k = 0; k < HEADS; k++) acc[k] = fmaf(s, __ldg(&w2[hh * HEADS + k]), acc[k]);
        }
        // values: chunk c (c=0,1) -> quarters 3c, 3c+1 hold heads 8c..8c+7
        float* row = smem + n * ROWQ * 4;
        #pragma unroll
        for (int c = 0; c < 2; c++) {
            float4 v0 = make_float4(acc[8*c+0], acc[8*c+1], acc[8*c+2], acc[8*c+3]);
            float4 v1 = make_float4(acc[8*c+4], acc[8*c+5], acc[8*c+6], acc[8*c+7]);
            ((float4*)row)[3*c]     = v0;
            ((float4*)row)[3*c + 1] = v1;
        }
    }
    __syncthreads();

    // ---------- phase 2b: fp16 slopes into quarter 3c+2 ----------
    for (int n = tid; n < NB; n += TPB) {
        const float* rA = smem + n * ROWQ * 4;
        const float* rN = rA + ROWQ * 4;
        #pragma unroll
        for (int c = 0; c < 2; c++) {
            __half2 s[4];
            #pragma unroll
            for (int m = 0; m < 4; m++) {
                int k = 8 * c + 2 * m;
                // value layout inside chunk: quarter 3c has heads 8c..+3, 3c+1 has +4..+7
                float a0 = rA[(3*c) * 4 + ((2*m)   & 3) + ((2*m)   >> 2) * 4];
                float a1 = rA[(3*c) * 4 + ((2*m+1) & 3) + ((2*m+1) >> 2) * 4];
                float n0 = rN[(3*c) * 4 + ((2*m)   & 3) + ((2*m)   >> 2) * 4];
                float n1 = rN[(3*c) * 4 + ((2*m+1) & 3) + ((2*m+1) >> 2) * 4];
                (void)k;
                s[m] = __floats2half2_rn(n0 - a0, n1 - a1);
            }
            float4 sq;
            memcpy(&sq, s, 16);
            ((float4*)(smem + n * ROWQ * 4))[3*c + 2] = sq;
        }
    }
    __syncthreads();

    // ---------- phase 3: main pair loop ----------
    const int q  = tid;                 // j-pair index 0..511
    const int j0 = q << 1;
    const size_t NN2 = (size_t)NPT * NPT / 2;

    const int nrow = BATCH * NPT;       // 4096
    int per = nrow / gridDim.x, rem = nrow % gridDim.x;
    int start, cnt;
    if ((int)blockIdx.x < rem) { cnt = per + 1; start = blockIdx.x * cnt; }
    else                       { cnt = per;     start = rem * (per + 1) + (blockIdx.x - rem) * per; }

    int bcur = -1;
    float cj0x=0, cj0y=0, cj0z=0, cj1x=0, cj1y=0, cj1z=0;

    for (int row = start; row < start + cnt; row++) {
        int b = row >> 10, i = row & 1023;
        if (b != bcur) {
            bcur = b;
            const float* cb = coords + ((size_t)b * NPT + j0) * 3;
            cj0x = cb[0]; cj0y = cb[1]; cj0z = cb[2];
            cj1x = cb[3]; cj1y = cb[4]; cj1z = cb[5];
        }
        const float* cip = coords + ((size_t)b * NPT + i) * 3;
        float cix = __ldg(cip), ciy = __ldg(cip + 1), ciz = __ldg(cip + 2);

        float t0, t1; int a0, a1;
        {
            float dx = cix - cj0x, dy = ciy - cj0y, dz = ciz - cj0z;
            float x  = sqrtf(fmaf(dx, dx, fmaf(dy, dy, dz * dz))) * invh;
            int bin  = min((int)x, NB - 1);
            t0 = x - (float)bin; a0 = bin * ROWQ;
        }
        {
            float dx = cix - cj1x, dy = ciy - cj1y, dz = ciz - cj1z;
            float x  = sqrtf(fmaf(dx, dx, fmaf(dy, dy, dz * dz))) * invh;
            int bin  = min((int)x, NB - 1);
            t1 = x - (float)bin; a1 = bin * ROWQ;
        }

        float2* po = (float2*)out + (size_t)b * HEADS * NN2 + (size_t)i * (NPT / 2) + q;
        #pragma unroll
        for (int c = 0; c < 2; c++) {
            float4 vA0 = lut4[a0 + 3*c], vA1 = lut4[a0 + 3*c + 1], sA = lut4[a0 + 3*c + 2];
            float4 vB0 = lut4[a1 + 3*c], vB1 = lut4[a1 + 3*c + 1], sB = lut4[a1 + 3*c + 2];
            const __half2* hA = (const __half2*)&sA;
            const __half2* hB = (const __half2*)&sB;
            const float* fA0 = (const float*)&vA0;
            const float* fA1 = (const float*)&vA1;
            const float* fB0 = (const float*)&vB0;
            const float* fB1 = (const float*)&vB1;
            #pragma unroll
            for (int m = 0; m < 4; m++) {
                float2 sa = __half22float2(hA[m]);
                float2 sb = __half22float2(hB[m]);
                int k0 = 2 * m;                       // heads 8c+k0, 8c+k0+1
                float va0 = (k0 < 4)     ? fA0[k0]       : fA1[k0 - 4];
                float va1 = (k0+1 < 4)   ? fA0[k0 + 1]   : fA1[k0 - 3];
                float vb0 = (k0 < 4)     ? fB0[k0]       : fB1[k0 - 4];
                float vb1 = (k0+1 < 4)   ? fB0[k0 + 1]   : fB1[k0 - 3];
                float2 r0, r1;
                r0.x = fmaf(t0, sa.x, va0); r0.y = fmaf(t1, sb.x, vb0);
                r1.x = fmaf(t0, sa.y, va1); r1.y = fmaf(t1, sb.y, vb1);
                po[(size_t)(8*c + k0)     * NN2] = r0;
                po[(size_t)(8*c + k0 + 1) * NN2] = r1;
            }
        }
    }
}

extern "C" void kernel_launch(void* const* d_in, const int* in_sizes, int n_in,
                              void* d_out, int out_size) {
    const float* coords = (const float*)d_in[0];
    const float* w1     = (const float*)d_in[1];
    const float* b1     = (const float*)d_in[2];
    const float* w2     = (const float*)d_in[3];
    const float* b2     = (const float*)d_in[4];
    float* out = (float*)d_out;

    const int smem_bytes = ((NB + 1) * ROWQ * 4 + 32) * (int)sizeof(float);  // ~57.6 KB
    cudaFuncSetAttribute(k_fused, cudaFuncAttributeMaxDynamicSharedMemorySize, smem_bytes);
    k_fused<<<GRID, TPB, smem_bytes>>>(coords, w1, b1, w2, b2, out);
}